// round 13
// baseline (speedup 1.0000x reference)
#include <cuda_runtime.h>
#include <cuda_bf16.h>
#include <cuda_fp16.h>
#include <cstdint>

// NT=32, HS=64, WS=64 (K), CL=96 (l/j), OD=128 (o), G=8
// b = nt*64 + hs in [0,2048). One problem per CTA.

__device__ __align__(16) __half g_scratch[2048 * 64 * 96];  // scr[b*6144 + d*96 + cl]

__device__ __forceinline__ float ex2f(float x) {
    float r;
    asm("ex2.approx.f32 %0, %1;" : "=f"(r) : "f"(x));
    return r;
}
__device__ __forceinline__ float rcpf(float x) {
    float r;
    asm("rcp.approx.f32 %0, %1;" : "=f"(r) : "f"(x));
    return r;
}

__device__ __forceinline__ void mma_k16(float* d, const uint32_t* a,
                                        uint32_t b0, uint32_t b1) {
    asm volatile(
        "mma.sync.aligned.m16n8k16.row.col.f32.bf16.bf16.f32 "
        "{%0,%1,%2,%3}, {%4,%5,%6,%7}, {%8,%9}, {%0,%1,%2,%3};"
        : "+f"(d[0]), "+f"(d[1]), "+f"(d[2]), "+f"(d[3])
        : "r"(a[0]), "r"(a[1]), "r"(a[2]), "r"(a[3]), "r"(b0), "r"(b1));
}

__device__ __forceinline__ uint32_t bpack(float lo, float hi) {
    __nv_bfloat162 t = __float22bfloat162_rn(make_float2(lo, hi));
    return *(uint32_t*)&t;
}
__device__ __forceinline__ float blo(uint32_t hw) {
    return __uint_as_float(hw << 16);
}
__device__ __forceinline__ float bhi(uint32_t hw) {
    return __uint_as_float(hw & 0xFFFF0000u);
}

// split float4 into bf16-high / bf16-low, store 8B to each buffer
__device__ __forceinline__ void split8(char* hb, char* lb, uint32_t off, float4 v) {
    __nv_bfloat162 h0 = __float22bfloat162_rn(make_float2(v.x, v.y));
    __nv_bfloat162 h1 = __float22bfloat162_rn(make_float2(v.z, v.w));
    float2 f0 = __bfloat1622float2(h0), f1 = __bfloat1622float2(h1);
    __nv_bfloat162 l0 = __float22bfloat162_rn(make_float2(v.x - f0.x, v.y - f0.y));
    __nv_bfloat162 l1 = __float22bfloat162_rn(make_float2(v.z - f1.x, v.w - f1.y));
    uint2 hv, lv;
    hv.x = *(uint32_t*)&h0; hv.y = *(uint32_t*)&h1;
    lv.x = *(uint32_t*)&l0; lv.y = *(uint32_t*)&l1;
    *(uint2*)(hb + off) = hv;
    *(uint2*)(lb + off) = lv;
}

// ---------------- shared memory layout ----------------
// Phase 1 (QKV GEMM operands; rows stride 144B). Dead after MMA barrier.
#define OFF_AH 0        // Wh: 128 x 144B
#define OFF_AL 18432    // Wl
#define OFF_XH 36864    // Xh: 96 x 144B
#define OFF_XL 50688    // Xl              (end 64512)
// Phase 2: per-warp attention buffers (alias phase 1), base w*PWB:
//   Q: 96 rows x 48B; 16 bf16 slots = [qh(c0..3) | ql(c0..3) | qh(c0..3) | 0]
//   K: 96 rows x 48B; slots = [kh | kh | kl | 0]
//   VH/VL: 8 c-rows x 208B of bf16 over j (96 used)
#define PWB  12544
#define O_Q  0
#define O_K  4608
#define O_VH 9216
#define O_VL 10880      // end 12544; x8 warps = 100352
// coefficients, float indices from smem base (byte 100352+):
#define CAQ 25088
#define CBQ 25216
#define CAS 25344
#define CAO 25352
#define CBO 25416
#define SMEM_BYTES 101920

extern "C" __global__ void __launch_bounds__(256, 2)
attn_fused_kernel(const float* __restrict__ x, const float* __restrict__ w_qkv,
                  const float* __restrict__ qg, const float* __restrict__ qb,
                  const float* __restrict__ qm, const float* __restrict__ qv,
                  const float* __restrict__ sg, const float* __restrict__ sb,
                  const float* __restrict__ smn, const float* __restrict__ svr,
                  const float* __restrict__ og, const float* __restrict__ ob,
                  const float* __restrict__ om, const float* __restrict__ ov) {
    extern __shared__ __align__(16) char smemc[];
    float* smem = (float*)smemc;
    const int tid  = threadIdx.x;
    const int lane = tid & 31;
    const int w    = tid >> 5;
    const int b    = blockIdx.x;
    const int nt   = b >> 6;
    const int hs   = b & 63;
    const int r0   = lane >> 2;   // 0..7
    const int m4   = lane & 3;    // 0..3

    // ---- BN coefficient precompute ----
    if (tid < 128) {
        float a = qg[tid] * rsqrtf(qv[tid] + 1e-5f);
        smem[CAQ + tid] = a;
        smem[CBQ + tid] = qb[tid] - qm[tid] * a;
    }
    if (tid < 64) {
        float a = og[tid] * rsqrtf(ov[tid] + 1e-5f);
        smem[CAO + tid] = a;
        smem[CBO + tid] = ob[tid] - om[tid] * a;
    }
    if (tid < 8) {
        smem[CAS + tid] = sg[tid] * rsqrtf(svr[tid] + 1e-5f);
        (void)sb; (void)smn;  // sim BN bias cancels inside softmax
    }

    // ---- operand prep: W split (A, 128 rows(o) x 64 bf16(i)) ----
#pragma unroll
    for (int u = 0; u < 8; u++) {
        int idx4 = tid + 256 * u;
        int o = idx4 >> 4, i4 = idx4 & 15;
        float4 v = *(const float4*)(w_qkv + idx4 * 4);
        split8(smemc + OFF_AH, smemc + OFF_AL, o * 144 + i4 * 8, v);
    }
    // ---- operand prep: X split (B, 96 rows(l) x 64 bf16(i)) ----
    {
        const float* xbase = x + (size_t)nt * 393216 + (size_t)hs * 64;
#pragma unroll
        for (int u = 0; u < 6; u++) {
            int idx = tid + 256 * u;
            int i4 = idx & 15, l = idx >> 4;
            float4 v = *(const float4*)(xbase + (size_t)l * 4096 + i4 * 4);
            split8(smemc + OFF_XH, smemc + OFF_XL, l * 144 + i4 * 8, v);
        }
    }
    __syncthreads();

    // ---- tensor-core QKV GEMM: warp w owns rows o in [16w, 16w+16) ----
    float d[12][4];
#pragma unroll
    for (int p = 0; p < 12; p++)
#pragma unroll
        for (int q = 0; q < 4; q++) d[p][q] = 0.f;
    {
        const int qk2 = m4 * 4;
        uint32_t ah[4][4];
#pragma unroll
        for (int k = 0; k < 4; k++) {
            uint32_t off = (uint32_t)(16 * w + r0) * 144 + 32 * k + qk2;
            ah[k][0] = *(const uint32_t*)(smemc + OFF_AH + off);
            ah[k][1] = *(const uint32_t*)(smemc + OFF_AH + off + 8 * 144);
            ah[k][2] = *(const uint32_t*)(smemc + OFF_AH + off + 16);
            ah[k][3] = *(const uint32_t*)(smemc + OFF_AH + off + 8 * 144 + 16);
        }
#pragma unroll
        for (int k = 0; k < 4; k++)
#pragma unroll
            for (int p = 0; p < 6; p++) {
                uint32_t boff = (uint32_t)(16 * p + r0) * 144 + 32 * k + qk2;
                uint32_t b0 = *(const uint32_t*)(smemc + OFF_XH + boff);
                uint32_t b1 = *(const uint32_t*)(smemc + OFF_XH + boff + 16);
                uint32_t b2 = *(const uint32_t*)(smemc + OFF_XH + boff + 8 * 144);
                uint32_t b3 = *(const uint32_t*)(smemc + OFF_XH + boff + 8 * 144 + 16);
                mma_k16(d[2 * p],     ah[k], b0, b1);
                mma_k16(d[2 * p + 1], ah[k], b2, b3);
            }
#pragma unroll
        for (int k = 0; k < 4; k++)
#pragma unroll
            for (int p = 0; p < 6; p++) {
                uint32_t boff = (uint32_t)(16 * p + r0) * 144 + 32 * k + qk2;
                uint32_t b0 = *(const uint32_t*)(smemc + OFF_XL + boff);
                uint32_t b1 = *(const uint32_t*)(smemc + OFF_XL + boff + 16);
                uint32_t b2 = *(const uint32_t*)(smemc + OFF_XL + boff + 8 * 144);
                uint32_t b3 = *(const uint32_t*)(smemc + OFF_XL + boff + 8 * 144 + 16);
                mma_k16(d[2 * p],     ah[k], b0, b1);
                mma_k16(d[2 * p + 1], ah[k], b2, b3);
            }
#pragma unroll
        for (int k = 0; k < 4; k++) {
            uint32_t off = (uint32_t)(16 * w + r0) * 144 + 32 * k + qk2;
            uint32_t al[4];
            al[0] = *(const uint32_t*)(smemc + OFF_AL + off);
            al[1] = *(const uint32_t*)(smemc + OFF_AL + off + 8 * 144);
            al[2] = *(const uint32_t*)(smemc + OFF_AL + off + 16);
            al[3] = *(const uint32_t*)(smemc + OFF_AL + off + 8 * 144 + 16);
#pragma unroll
            for (int p = 0; p < 6; p++) {
                uint32_t boff = (uint32_t)(16 * p + r0) * 144 + 32 * k + qk2;
                uint32_t b0 = *(const uint32_t*)(smemc + OFF_XH + boff);
                uint32_t b1 = *(const uint32_t*)(smemc + OFF_XH + boff + 16);
                uint32_t b2 = *(const uint32_t*)(smemc + OFF_XH + boff + 8 * 144);
                uint32_t b3 = *(const uint32_t*)(smemc + OFF_XH + boff + 8 * 144 + 16);
                mma_k16(d[2 * p],     al, b0, b1);
                mma_k16(d[2 * p + 1], al, b2, b3);
            }
        }
    }
    __syncthreads();   // operand reads done; per-warp buffers may alias now

    char* wb = smemc + w * PWB;

    // ---- zero the k-slot padding (bytes 24..31 of each Q/K row) ----
#pragma unroll
    for (int u = 0; u < 3; u++) {
        int row = lane + 32 * u;
        *(uint64_t*)(wb + O_Q + row * 48 + 24) = 0ull;
        *(uint64_t*)(wb + O_K + row * 48 + 24) = 0ull;
    }

    // ---- epilogue: BN; q/k/v into attention operand buffers ----
    {
        const float sc = smem[CAS + w] * 1.4426950408889634f;  // ag/ln2
        const int o = 16 * w + r0;
        float A, B;
        if (r0 < 4) { A = smem[CAQ + o] * sc; B = smem[CBQ + o] * sc; }
        else        { A = smem[CAQ + o];      B = smem[CBQ + o]; }
        const float av = smem[CAQ + o + 8], bv = smem[CBQ + o + 8];
#pragma unroll
        for (int p = 0; p < 12; p++) {
            int l0 = 8 * p + 2 * m4;
            float v0 = d[p][0] * A + B, v1 = d[p][1] * A + B;
            __nv_bfloat16 h0 = __float2bfloat16_rn(v0);
            __nv_bfloat16 h1 = __float2bfloat16_rn(v1);
            __nv_bfloat16 g0 = __float2bfloat16_rn(v0 - __bfloat162float(h0));
            __nv_bfloat16 g1 = __float2bfloat16_rn(v1 - __bfloat162float(h1));
            if (r0 < 4) {
                int c = r0;
                char* q0p = wb + O_Q + l0 * 48;
                char* q1p = q0p + 48;
                *(__nv_bfloat16*)(q0p + 2 * c)       = h0;
                *(__nv_bfloat16*)(q0p + 2 * (8 + c)) = h0;
                *(__nv_bfloat16*)(q0p + 2 * (4 + c)) = g0;
                *(__nv_bfloat16*)(q1p + 2 * c)       = h1;
                *(__nv_bfloat16*)(q1p + 2 * (8 + c)) = h1;
                *(__nv_bfloat16*)(q1p + 2 * (4 + c)) = g1;
            } else {
                int c = r0 - 4;
                char* k0p = wb + O_K + l0 * 48;
                char* k1p = k0p + 48;
                *(__nv_bfloat16*)(k0p + 2 * c)       = h0;
                *(__nv_bfloat16*)(k0p + 2 * (4 + c)) = h0;
                *(__nv_bfloat16*)(k0p + 2 * (8 + c)) = g0;
                *(__nv_bfloat16*)(k1p + 2 * c)       = h1;
                *(__nv_bfloat16*)(k1p + 2 * (4 + c)) = h1;
                *(__nv_bfloat16*)(k1p + 2 * (8 + c)) = g1;
            }
            float vb0 = d[p][2] * av + bv, vb1 = d[p][3] * av + bv;
            uint32_t hv = bpack(vb0, vb1);
            uint32_t lv = bpack(vb0 - blo(hv), vb1 - bhi(hv));
            *(uint32_t*)(wb + O_VH + r0 * 208 + l0 * 2) = hv;
            *(uint32_t*)(wb + O_VL + r0 * 208 + l0 * 2) = lv;
        }
    }
    __syncwarp();   // buffers are warp-private

    // ---- HMMA attention: all-k16, two m-tiles interleaved per iteration ----
    {
        __half* scr = &g_scratch[(size_t)b * 6144];
        const int d0 = 8 * w + 2 * m4;
        const float ao0 = smem[CAO + d0],     bo0 = smem[CBO + d0];
        const float ao1 = smem[CAO + d0 + 1], bo1 = smem[CBO + d0 + 1];

#pragma unroll 1
        for (int tp = 0; tp < 3; tp++) {
            uint32_t qa0[4], qa1[4];
            {
                uint32_t qoff = (uint32_t)(32 * tp + r0) * 48 + 4 * m4;
                qa0[0] = *(const uint32_t*)(wb + O_Q + qoff);
                qa0[1] = *(const uint32_t*)(wb + O_Q + qoff + 8 * 48);
                qa0[2] = *(const uint32_t*)(wb + O_Q + qoff + 16);
                qa0[3] = *(const uint32_t*)(wb + O_Q + qoff + 8 * 48 + 16);
                uint32_t qoff1 = qoff + 16 * 48;
                qa1[0] = *(const uint32_t*)(wb + O_Q + qoff1);
                qa1[1] = *(const uint32_t*)(wb + O_Q + qoff1 + 8 * 48);
                qa1[2] = *(const uint32_t*)(wb + O_Q + qoff1 + 16);
                qa1[3] = *(const uint32_t*)(wb + O_Q + qoff1 + 8 * 48 + 16);
            }
            float a0A[4] = {0.f, 0.f, 0.f, 0.f}, a0B[4] = {0.f, 0.f, 0.f, 0.f};
            float a1A[4] = {0.f, 0.f, 0.f, 0.f}, a1B[4] = {0.f, 0.f, 0.f, 0.f};
            float s0_lo = 0.f, s0_hi = 0.f, s1_lo = 0.f, s1_hi = 0.f;

#pragma unroll 2
            for (int blk = 0; blk < 6; blk++) {
                uint32_t eh0[4], el0[4], eh1[4], el1[4];
#pragma unroll
                for (int sub = 0; sub < 2; sub++) {
                    int ch = 2 * blk + sub;
                    uint32_t koff = (uint32_t)(8 * ch + r0) * 48 + 4 * m4;
                    uint32_t kb0 = *(const uint32_t*)(wb + O_K + koff);
                    uint32_t kb1 = *(const uint32_t*)(wb + O_K + koff + 16);

                    float S0[4] = {0.f, 0.f, 0.f, 0.f};
                    float S1[4] = {0.f, 0.f, 0.f, 0.f};
                    mma_k16(S0, qa0, kb0, kb1);   // qh*kh + ql*kh + qh*kl
                    mma_k16(S1, qa1, kb0, kb1);

                    float e00 = ex2f(S0[0]), e01 = ex2f(S0[1]);
                    float e02 = ex2f(S0[2]), e03 = ex2f(S0[3]);
                    s0_lo += e00 + e01;
                    s0_hi += e02 + e03;
                    uint32_t p00 = bpack(e00, e01), p01 = bpack(e02, e03);
                    eh0[2 * sub]     = p00;
                    eh0[2 * sub + 1] = p01;
                    el0[2 * sub]     = bpack(e00 - blo(p00), e01 - bhi(p00));
                    el0[2 * sub + 1] = bpack(e02 - blo(p01), e03 - bhi(p01));

                    float e10 = ex2f(S1[0]), e11 = ex2f(S1[1]);
                    float e12 = ex2f(S1[2]), e13 = ex2f(S1[3]);
                    s1_lo += e10 + e11;
                    s1_hi += e12 + e13;
                    uint32_t p10 = bpack(e10, e11), p11 = bpack(e12, e13);
                    eh1[2 * sub]     = p10;
                    eh1[2 * sub + 1] = p11;
                    el1[2 * sub]     = bpack(e10 - blo(p10), e11 - bhi(p10));
                    el1[2 * sub + 1] = bpack(e12 - blo(p11), e13 - bhi(p11));
                }
                uint32_t voff = (uint32_t)r0 * 208 + 32 * blk + 4 * m4;
                uint32_t vh0 = *(const uint32_t*)(wb + O_VH + voff);
                uint32_t vh1 = *(const uint32_t*)(wb + O_VH + voff + 16);
                uint32_t vl0 = *(const uint32_t*)(wb + O_VL + voff);
                uint32_t vl1 = *(const uint32_t*)(wb + O_VL + voff + 16);
                mma_k16(a0A, eh0, vh0, vh1);
                mma_k16(a1A, eh1, vh0, vh1);
                mma_k16(a0B, el0, vh0, vh1);
                mma_k16(a1B, el1, vh0, vh1);
                mma_k16(a0B, eh0, vl0, vl1);
                mma_k16(a1B, eh1, vl0, vl1);
            }

            s0_lo += __shfl_xor_sync(0xffffffffu, s0_lo, 1);
            s0_lo += __shfl_xor_sync(0xffffffffu, s0_lo, 2);
            s0_hi += __shfl_xor_sync(0xffffffffu, s0_hi, 1);
            s0_hi += __shfl_xor_sync(0xffffffffu, s0_hi, 2);
            s1_lo += __shfl_xor_sync(0xffffffffu, s1_lo, 1);
            s1_lo += __shfl_xor_sync(0xffffffffu, s1_lo, 2);
            s1_hi += __shfl_xor_sync(0xffffffffu, s1_hi, 1);
            s1_hi += __shfl_xor_sync(0xffffffffu, s1_hi, 2);
            float r0l = rcpf(s0_lo), r0h = rcpf(s0_hi);
            float r1l = rcpf(s1_lo), r1h = rcpf(s1_hi);

            int i0 = 32 * tp + r0;
            scr[d0 * 96 + i0]            = __float2half_rn((a0A[0] + a0B[0]) * r0l * ao0 + bo0);
            scr[(d0 + 1) * 96 + i0]      = __float2half_rn((a0A[1] + a0B[1]) * r0l * ao1 + bo1);
            scr[d0 * 96 + i0 + 8]        = __float2half_rn((a0A[2] + a0B[2]) * r0h * ao0 + bo0);
            scr[(d0 + 1) * 96 + i0 + 8]  = __float2half_rn((a0A[3] + a0B[3]) * r0h * ao1 + bo1);
            int i1 = i0 + 16;
            scr[d0 * 96 + i1]            = __float2half_rn((a1A[0] + a1B[0]) * r1l * ao0 + bo0);
            scr[(d0 + 1) * 96 + i1]      = __float2half_rn((a1A[1] + a1B[1]) * r1l * ao1 + bo1);
            scr[d0 * 96 + i1 + 8]        = __float2half_rn((a1A[2] + a1B[2]) * r1h * ao0 + bo0);
            scr[(d0 + 1) * 96 + i1 + 8]  = __float2half_rn((a1A[3] + a1B[3]) * r1h * ao1 + bo1);
        }
    }
}

// Permute scr[(nt*64+hs)*6144 + d*96 + cl] (fp16) -> out[((nt*96+cl)*64 + d)*64 + hs]
extern "C" __global__ void __launch_bounds__(256)
attn_transpose_kernel(float* __restrict__ out) {
    __shared__ float tile[64 * 97];
    const int nt = blockIdx.x >> 6;
    const int d  = blockIdx.x & 63;

    const __half* src = g_scratch + (size_t)nt * 393216 + (size_t)d * 96;
#pragma unroll
    for (int u = 0; u < 3; u++) {
        int idx = threadIdx.x + 256 * u;
        int h = idx / 12, c8 = idx % 12;
        uint4 raw = *(const uint4*)(src + (size_t)h * 6144 + c8 * 8);
        const __half2* hp = (const __half2*)&raw;
        float* dst = &tile[h * 97 + c8 * 8];
#pragma unroll
        for (int e = 0; e < 4; e++) {
            float2 f = __half22float2(hp[e]);
            dst[2 * e]     = f.x;
            dst[2 * e + 1] = f.y;
        }
    }
    __syncthreads();

    float* dst = out + (size_t)nt * 393216 + (size_t)d * 64;
#pragma unroll
    for (int u = 0; u < 6; u++) {
        int idx = threadIdx.x + 256 * u;     // 0..1535
        int cl = idx >> 4, h4 = idx & 15;
        float4 v;
        v.x = tile[(4 * h4 + 0) * 97 + cl];
        v.y = tile[(4 * h4 + 1) * 97 + cl];
        v.z = tile[(4 * h4 + 2) * 97 + cl];
        v.w = tile[(4 * h4 + 3) * 97 + cl];
        *(float4*)(dst + (size_t)cl * 4096 + 4 * h4) = v;
    }
}

extern "C" void kernel_launch(void* const* d_in, const int* in_sizes, int n_in,
                              void* d_out, int out_size) {
    const float* x   = (const float*)d_in[0];
    const float* wq  = (const float*)d_in[1];
    const float* qg  = (const float*)d_in[2];
    const float* qb  = (const float*)d_in[3];
    const float* qm  = (const float*)d_in[4];
    const float* qv  = (const float*)d_in[5];
    const float* sg  = (const float*)d_in[6];
    const float* sb  = (const float*)d_in[7];
    const float* smn = (const float*)d_in[8];
    const float* svr = (const float*)d_in[9];
    const float* og  = (const float*)d_in[10];
    const float* ob  = (const float*)d_in[11];
    const float* om  = (const float*)d_in[12];
    const float* ov  = (const float*)d_in[13];
    float* out = (float*)d_out;

    cudaFuncSetAttribute(attn_fused_kernel,
                         cudaFuncAttributeMaxDynamicSharedMemorySize, SMEM_BYTES);

    attn_fused_kernel<<<2048, 256, SMEM_BYTES>>>(x, wq, qg, qb, qm, qv, sg, sb,
                                                 smn, svr, og, ob, om, ov);
    attn_transpose_kernel<<<2048, 256>>>(out);
}

// round 14
// speedup vs baseline: 1.0359x; 1.0359x over previous
#include <cuda_runtime.h>
#include <cuda_bf16.h>
#include <cuda_fp16.h>
#include <cstdint>

// NT=32, HS=64, WS=64 (K), CL=96 (l/j), OD=128 (o), G=8
// b = nt*64 + hs in [0,2048). One problem per CTA.
// Scratch layout: scr[b][cl][d]  (fp16; d contiguous)

__device__ __align__(16) __half g_scratch[2048 * 96 * 64];

__device__ __forceinline__ float ex2f(float x) {
    float r;
    asm("ex2.approx.f32 %0, %1;" : "=f"(r) : "f"(x));
    return r;
}
__device__ __forceinline__ float rcpf(float x) {
    float r;
    asm("rcp.approx.f32 %0, %1;" : "=f"(r) : "f"(x));
    return r;
}

__device__ __forceinline__ void mma_k16(float* d, const uint32_t* a,
                                        uint32_t b0, uint32_t b1) {
    asm volatile(
        "mma.sync.aligned.m16n8k16.row.col.f32.bf16.bf16.f32 "
        "{%0,%1,%2,%3}, {%4,%5,%6,%7}, {%8,%9}, {%0,%1,%2,%3};"
        : "+f"(d[0]), "+f"(d[1]), "+f"(d[2]), "+f"(d[3])
        : "r"(a[0]), "r"(a[1]), "r"(a[2]), "r"(a[3]), "r"(b0), "r"(b1));
}

__device__ __forceinline__ uint32_t bpack(float lo, float hi) {
    __nv_bfloat162 t = __float22bfloat162_rn(make_float2(lo, hi));
    return *(uint32_t*)&t;
}
__device__ __forceinline__ float blo(uint32_t hw) {
    return __uint_as_float(hw << 16);
}
__device__ __forceinline__ float bhi(uint32_t hw) {
    return __uint_as_float(hw & 0xFFFF0000u);
}

// split float4 into bf16-high / bf16-low, store 8B to each buffer
__device__ __forceinline__ void split8(char* hb, char* lb, uint32_t off, float4 v) {
    __nv_bfloat162 h0 = __float22bfloat162_rn(make_float2(v.x, v.y));
    __nv_bfloat162 h1 = __float22bfloat162_rn(make_float2(v.z, v.w));
    float2 f0 = __bfloat1622float2(h0), f1 = __bfloat1622float2(h1);
    __nv_bfloat162 l0 = __float22bfloat162_rn(make_float2(v.x - f0.x, v.y - f0.y));
    __nv_bfloat162 l1 = __float22bfloat162_rn(make_float2(v.z - f1.x, v.w - f1.y));
    uint2 hv, lv;
    hv.x = *(uint32_t*)&h0; hv.y = *(uint32_t*)&h1;
    lv.x = *(uint32_t*)&l0; lv.y = *(uint32_t*)&l1;
    *(uint2*)(hb + off) = hv;
    *(uint2*)(lb + off) = lv;
}

// ---------------- shared memory layout ----------------
// Phase 1 (QKV GEMM operands; rows stride 144B). Dead after MMA barrier.
#define OFF_AH 0        // Wh: 128 x 144B
#define OFF_AL 18432    // Wl
#define OFF_XH 36864    // Xh: 96 x 144B
#define OFF_XL 50688    // Xl              (end 64512)
// Phase 2: per-warp attention buffers (alias phase 1), base w*PWB:
//   Q: 96 rows x 48B; 16 bf16 slots = [qh(c0..3) | ql(c0..3) | qh(c0..3) | 0]
//   K: 96 rows x 48B; slots = [kh | kh | kl | 0]
//   VH/VL: 8 c-rows x 208B of bf16 over j (96 used)
#define PWB  12544
#define O_Q  0
#define O_K  4608
#define O_VH 9216
#define O_VL 10880      // end 12544; x8 warps = 100352
// coefficients, float indices from smem base (byte 100352+):
#define CAQ 25088
#define CBQ 25216
#define CAS 25344
#define CAO 25352
#define CBO 25416
#define SMEM_BYTES 101920

extern "C" __global__ void __launch_bounds__(256, 2)
attn_fused_kernel(const float* __restrict__ x, const float* __restrict__ w_qkv,
                  const float* __restrict__ qg, const float* __restrict__ qb,
                  const float* __restrict__ qm, const float* __restrict__ qv,
                  const float* __restrict__ sg, const float* __restrict__ sb,
                  const float* __restrict__ smn, const float* __restrict__ svr,
                  const float* __restrict__ og, const float* __restrict__ ob,
                  const float* __restrict__ om, const float* __restrict__ ov) {
    extern __shared__ __align__(16) char smemc[];
    float* smem = (float*)smemc;
    const int tid  = threadIdx.x;
    const int lane = tid & 31;
    const int w    = tid >> 5;
    const int b    = blockIdx.x;
    const int nt   = b >> 6;
    const int hs   = b & 63;
    const int r0   = lane >> 2;   // 0..7
    const int m4   = lane & 3;    // 0..3

    // ---- BN coefficient precompute ----
    if (tid < 128) {
        float a = qg[tid] * rsqrtf(qv[tid] + 1e-5f);
        smem[CAQ + tid] = a;
        smem[CBQ + tid] = qb[tid] - qm[tid] * a;
    }
    if (tid < 64) {
        float a = og[tid] * rsqrtf(ov[tid] + 1e-5f);
        smem[CAO + tid] = a;
        smem[CBO + tid] = ob[tid] - om[tid] * a;
    }
    if (tid < 8) {
        smem[CAS + tid] = sg[tid] * rsqrtf(svr[tid] + 1e-5f);
        (void)sb; (void)smn;  // sim BN bias cancels inside softmax
    }

    // ---- operand prep: W split (A, 128 rows(o) x 64 bf16(i)) ----
#pragma unroll
    for (int u = 0; u < 8; u++) {
        int idx4 = tid + 256 * u;
        int o = idx4 >> 4, i4 = idx4 & 15;
        float4 v = *(const float4*)(w_qkv + idx4 * 4);
        split8(smemc + OFF_AH, smemc + OFF_AL, o * 144 + i4 * 8, v);
    }
    // ---- operand prep: X split (B, 96 rows(l) x 64 bf16(i)) ----
    {
        const float* xbase = x + (size_t)nt * 393216 + (size_t)hs * 64;
#pragma unroll
        for (int u = 0; u < 6; u++) {
            int idx = tid + 256 * u;
            int i4 = idx & 15, l = idx >> 4;
            float4 v = *(const float4*)(xbase + (size_t)l * 4096 + i4 * 4);
            split8(smemc + OFF_XH, smemc + OFF_XL, l * 144 + i4 * 8, v);
        }
    }
    __syncthreads();

    // ---- tensor-core QKV GEMM: warp w owns rows o in [16w, 16w+16) ----
    float d[12][4];
#pragma unroll
    for (int p = 0; p < 12; p++)
#pragma unroll
        for (int q = 0; q < 4; q++) d[p][q] = 0.f;
    {
        const int qk2 = m4 * 4;
        uint32_t ah[4][4];
#pragma unroll
        for (int k = 0; k < 4; k++) {
            uint32_t off = (uint32_t)(16 * w + r0) * 144 + 32 * k + qk2;
            ah[k][0] = *(const uint32_t*)(smemc + OFF_AH + off);
            ah[k][1] = *(const uint32_t*)(smemc + OFF_AH + off + 8 * 144);
            ah[k][2] = *(const uint32_t*)(smemc + OFF_AH + off + 16);
            ah[k][3] = *(const uint32_t*)(smemc + OFF_AH + off + 8 * 144 + 16);
        }
#pragma unroll
        for (int k = 0; k < 4; k++)
#pragma unroll
            for (int p = 0; p < 6; p++) {
                uint32_t boff = (uint32_t)(16 * p + r0) * 144 + 32 * k + qk2;
                uint32_t b0 = *(const uint32_t*)(smemc + OFF_XH + boff);
                uint32_t b1 = *(const uint32_t*)(smemc + OFF_XH + boff + 16);
                uint32_t b2 = *(const uint32_t*)(smemc + OFF_XH + boff + 8 * 144);
                uint32_t b3 = *(const uint32_t*)(smemc + OFF_XH + boff + 8 * 144 + 16);
                mma_k16(d[2 * p],     ah[k], b0, b1);
                mma_k16(d[2 * p + 1], ah[k], b2, b3);
            }
#pragma unroll
        for (int k = 0; k < 4; k++)
#pragma unroll
            for (int p = 0; p < 6; p++) {
                uint32_t boff = (uint32_t)(16 * p + r0) * 144 + 32 * k + qk2;
                uint32_t b0 = *(const uint32_t*)(smemc + OFF_XL + boff);
                uint32_t b1 = *(const uint32_t*)(smemc + OFF_XL + boff + 16);
                uint32_t b2 = *(const uint32_t*)(smemc + OFF_XL + boff + 8 * 144);
                uint32_t b3 = *(const uint32_t*)(smemc + OFF_XL + boff + 8 * 144 + 16);
                mma_k16(d[2 * p],     ah[k], b0, b1);
                mma_k16(d[2 * p + 1], ah[k], b2, b3);
            }
#pragma unroll
        for (int k = 0; k < 4; k++) {
            uint32_t off = (uint32_t)(16 * w + r0) * 144 + 32 * k + qk2;
            uint32_t al[4];
            al[0] = *(const uint32_t*)(smemc + OFF_AL + off);
            al[1] = *(const uint32_t*)(smemc + OFF_AL + off + 8 * 144);
            al[2] = *(const uint32_t*)(smemc + OFF_AL + off + 16);
            al[3] = *(const uint32_t*)(smemc + OFF_AL + off + 8 * 144 + 16);
#pragma unroll
            for (int p = 0; p < 6; p++) {
                uint32_t boff = (uint32_t)(16 * p + r0) * 144 + 32 * k + qk2;
                uint32_t b0 = *(const uint32_t*)(smemc + OFF_XH + boff);
                uint32_t b1 = *(const uint32_t*)(smemc + OFF_XH + boff + 16);
                uint32_t b2 = *(const uint32_t*)(smemc + OFF_XH + boff + 8 * 144);
                uint32_t b3 = *(const uint32_t*)(smemc + OFF_XH + boff + 8 * 144 + 16);
                mma_k16(d[2 * p],     al, b0, b1);
                mma_k16(d[2 * p + 1], al, b2, b3);
            }
        }
    }
    __syncthreads();   // operand reads done; per-warp buffers may alias now

    char* wb = smemc + w * PWB;

    // ---- zero the k-slot padding (bytes 24..31 of each Q/K row) ----
#pragma unroll
    for (int u = 0; u < 3; u++) {
        int row = lane + 32 * u;
        *(uint64_t*)(wb + O_Q + row * 48 + 24) = 0ull;
        *(uint64_t*)(wb + O_K + row * 48 + 24) = 0ull;
    }

    // ---- epilogue: BN; q/k/v into attention operand buffers ----
    {
        const float sc = smem[CAS + w] * 1.4426950408889634f;  // ag/ln2
        const int o = 16 * w + r0;
        float A, B;
        if (r0 < 4) { A = smem[CAQ + o] * sc; B = smem[CBQ + o] * sc; }
        else        { A = smem[CAQ + o];      B = smem[CBQ + o]; }
        const float av = smem[CAQ + o + 8], bv = smem[CBQ + o + 8];
#pragma unroll
        for (int p = 0; p < 12; p++) {
            int l0 = 8 * p + 2 * m4;
            float v0 = d[p][0] * A + B, v1 = d[p][1] * A + B;
            __nv_bfloat16 h0 = __float2bfloat16_rn(v0);
            __nv_bfloat16 h1 = __float2bfloat16_rn(v1);
            __nv_bfloat16 g0 = __float2bfloat16_rn(v0 - __bfloat162float(h0));
            __nv_bfloat16 g1 = __float2bfloat16_rn(v1 - __bfloat162float(h1));
            if (r0 < 4) {
                int c = r0;
                char* q0p = wb + O_Q + l0 * 48;
                char* q1p = q0p + 48;
                *(__nv_bfloat16*)(q0p + 2 * c)       = h0;
                *(__nv_bfloat16*)(q0p + 2 * (8 + c)) = h0;
                *(__nv_bfloat16*)(q0p + 2 * (4 + c)) = g0;
                *(__nv_bfloat16*)(q1p + 2 * c)       = h1;
                *(__nv_bfloat16*)(q1p + 2 * (8 + c)) = h1;
                *(__nv_bfloat16*)(q1p + 2 * (4 + c)) = g1;
            } else {
                int c = r0 - 4;
                char* k0p = wb + O_K + l0 * 48;
                char* k1p = k0p + 48;
                *(__nv_bfloat16*)(k0p + 2 * c)       = h0;
                *(__nv_bfloat16*)(k0p + 2 * (4 + c)) = h0;
                *(__nv_bfloat16*)(k0p + 2 * (8 + c)) = g0;
                *(__nv_bfloat16*)(k1p + 2 * c)       = h1;
                *(__nv_bfloat16*)(k1p + 2 * (4 + c)) = h1;
                *(__nv_bfloat16*)(k1p + 2 * (8 + c)) = g1;
            }
            float vb0 = d[p][2] * av + bv, vb1 = d[p][3] * av + bv;
            uint32_t hv = bpack(vb0, vb1);
            uint32_t lv = bpack(vb0 - blo(hv), vb1 - bhi(hv));
            *(uint32_t*)(wb + O_VH + r0 * 208 + l0 * 2) = hv;
            *(uint32_t*)(wb + O_VL + r0 * 208 + l0 * 2) = lv;
        }
    }
    __syncwarp();   // buffers are warp-private

    // ---- HMMA attention: all-k16, two m-tiles interleaved per iteration ----
    {
        __half2* scr2 = (__half2*)(g_scratch + (size_t)b * 6144);
        const int d0 = 8 * w + 2 * m4;
        const int dh = d0 >> 1;
        const float ao0 = smem[CAO + d0],     bo0 = smem[CBO + d0];
        const float ao1 = smem[CAO + d0 + 1], bo1 = smem[CBO + d0 + 1];

#pragma unroll 1
        for (int tp = 0; tp < 3; tp++) {
            uint32_t qa0[4], qa1[4];
            {
                uint32_t qoff = (uint32_t)(32 * tp + r0) * 48 + 4 * m4;
                qa0[0] = *(const uint32_t*)(wb + O_Q + qoff);
                qa0[1] = *(const uint32_t*)(wb + O_Q + qoff + 8 * 48);
                qa0[2] = *(const uint32_t*)(wb + O_Q + qoff + 16);
                qa0[3] = *(const uint32_t*)(wb + O_Q + qoff + 8 * 48 + 16);
                uint32_t qoff1 = qoff + 16 * 48;
                qa1[0] = *(const uint32_t*)(wb + O_Q + qoff1);
                qa1[1] = *(const uint32_t*)(wb + O_Q + qoff1 + 8 * 48);
                qa1[2] = *(const uint32_t*)(wb + O_Q + qoff1 + 16);
                qa1[3] = *(const uint32_t*)(wb + O_Q + qoff1 + 8 * 48 + 16);
            }
            float a0A[4] = {0.f, 0.f, 0.f, 0.f}, a0B[4] = {0.f, 0.f, 0.f, 0.f};
            float a1A[4] = {0.f, 0.f, 0.f, 0.f}, a1B[4] = {0.f, 0.f, 0.f, 0.f};
            float s0_lo = 0.f, s0_hi = 0.f, s1_lo = 0.f, s1_hi = 0.f;

#pragma unroll 2
            for (int blk = 0; blk < 6; blk++) {
                uint32_t eh0[4], el0[4], eh1[4], el1[4];
#pragma unroll
                for (int sub = 0; sub < 2; sub++) {
                    int ch = 2 * blk + sub;
                    uint32_t koff = (uint32_t)(8 * ch + r0) * 48 + 4 * m4;
                    uint32_t kb0 = *(const uint32_t*)(wb + O_K + koff);
                    uint32_t kb1 = *(const uint32_t*)(wb + O_K + koff + 16);

                    float S0[4] = {0.f, 0.f, 0.f, 0.f};
                    float S1[4] = {0.f, 0.f, 0.f, 0.f};
                    mma_k16(S0, qa0, kb0, kb1);   // qh*kh + ql*kh + qh*kl
                    mma_k16(S1, qa1, kb0, kb1);

                    float e00 = ex2f(S0[0]), e01 = ex2f(S0[1]);
                    float e02 = ex2f(S0[2]), e03 = ex2f(S0[3]);
                    s0_lo += e00 + e01;
                    s0_hi += e02 + e03;
                    uint32_t p00 = bpack(e00, e01), p01 = bpack(e02, e03);
                    eh0[2 * sub]     = p00;
                    eh0[2 * sub + 1] = p01;
                    el0[2 * sub]     = bpack(e00 - blo(p00), e01 - bhi(p00));
                    el0[2 * sub + 1] = bpack(e02 - blo(p01), e03 - bhi(p01));

                    float e10 = ex2f(S1[0]), e11 = ex2f(S1[1]);
                    float e12 = ex2f(S1[2]), e13 = ex2f(S1[3]);
                    s1_lo += e10 + e11;
                    s1_hi += e12 + e13;
                    uint32_t p10 = bpack(e10, e11), p11 = bpack(e12, e13);
                    eh1[2 * sub]     = p10;
                    eh1[2 * sub + 1] = p11;
                    el1[2 * sub]     = bpack(e10 - blo(p10), e11 - bhi(p10));
                    el1[2 * sub + 1] = bpack(e12 - blo(p11), e13 - bhi(p11));
                }
                uint32_t voff = (uint32_t)r0 * 208 + 32 * blk + 4 * m4;
                uint32_t vh0 = *(const uint32_t*)(wb + O_VH + voff);
                uint32_t vh1 = *(const uint32_t*)(wb + O_VH + voff + 16);
                uint32_t vl0 = *(const uint32_t*)(wb + O_VL + voff);
                uint32_t vl1 = *(const uint32_t*)(wb + O_VL + voff + 16);
                mma_k16(a0A, eh0, vh0, vh1);
                mma_k16(a1A, eh1, vh0, vh1);
                mma_k16(a0B, el0, vh0, vh1);
                mma_k16(a1B, el1, vh0, vh1);
                mma_k16(a0B, eh0, vl0, vl1);
                mma_k16(a1B, eh1, vl0, vl1);
            }

            s0_lo += __shfl_xor_sync(0xffffffffu, s0_lo, 1);
            s0_lo += __shfl_xor_sync(0xffffffffu, s0_lo, 2);
            s0_hi += __shfl_xor_sync(0xffffffffu, s0_hi, 1);
            s0_hi += __shfl_xor_sync(0xffffffffu, s0_hi, 2);
            s1_lo += __shfl_xor_sync(0xffffffffu, s1_lo, 1);
            s1_lo += __shfl_xor_sync(0xffffffffu, s1_lo, 2);
            s1_hi += __shfl_xor_sync(0xffffffffu, s1_hi, 1);
            s1_hi += __shfl_xor_sync(0xffffffffu, s1_hi, 2);
            float r0l = rcpf(s0_lo), r0h = rcpf(s0_hi);
            float r1l = rcpf(s1_lo), r1h = rcpf(s1_hi);

            int i0 = 32 * tp + r0;
            scr2[i0 * 32 + dh] = __floats2half2_rn(
                (a0A[0] + a0B[0]) * r0l * ao0 + bo0,
                (a0A[1] + a0B[1]) * r0l * ao1 + bo1);
            scr2[(i0 + 8) * 32 + dh] = __floats2half2_rn(
                (a0A[2] + a0B[2]) * r0h * ao0 + bo0,
                (a0A[3] + a0B[3]) * r0h * ao1 + bo1);
            int i1 = i0 + 16;
            scr2[i1 * 32 + dh] = __floats2half2_rn(
                (a1A[0] + a1B[0]) * r1l * ao0 + bo0,
                (a1A[1] + a1B[1]) * r1l * ao1 + bo1);
            scr2[(i1 + 8) * 32 + dh] = __floats2half2_rn(
                (a1A[2] + a1B[2]) * r1h * ao0 + bo0,
                (a1A[3] + a1B[3]) * r1h * ao1 + bo1);
        }
    }
}

// Permute scr[(nt*64+hs)][cl][d] (fp16) -> out[((nt*96+cl)*64 + d)*64 + hs]
// One CTA per (nt, cl): reads 64(hs) x 64(d) fp16 tile, writes 4096 floats.
extern "C" __global__ void __launch_bounds__(256)
attn_transpose_kernel(float* __restrict__ out) {
    __shared__ uint32_t tile[64 * 33];   // fp16 rows: hs x 64d, stride 33 words
    const int nt = blockIdx.x / 96;
    const int cl = blockIdx.x % 96;

    const __half* src = g_scratch + ((size_t)nt * 64) * 6144 + cl * 64;
#pragma unroll
    for (int u = 0; u < 2; u++) {
        int idx = threadIdx.x + 256 * u;     // 0..511
        int hs = idx >> 3, d8 = idx & 7;
        uint4 v = *(const uint4*)(src + (size_t)hs * 6144 + 8 * d8);
        uint32_t* dst = &tile[33 * hs + 4 * d8];
        dst[0] = v.x; dst[1] = v.y; dst[2] = v.z; dst[3] = v.w;
    }
    __syncthreads();

    const __half* th = (const __half*)tile;   // index: hs*66 + d
    float* dst = out + ((size_t)nt * 96 + cl) * 4096;
#pragma unroll
    for (int u = 0; u < 4; u++) {
        int j = threadIdx.x + 256 * u;       // 0..1023
        int d = j >> 4, h4 = j & 15;
        float4 v;
        v.x = __half2float(th[(4 * h4 + 0) * 66 + d]);
        v.y = __half2float(th[(4 * h4 + 1) * 66 + d]);
        v.z = __half2float(th[(4 * h4 + 2) * 66 + d]);
        v.w = __half2float(th[(4 * h4 + 3) * 66 + d]);
        *(float4*)(dst + d * 64 + 4 * h4) = v;
    }
}

extern "C" void kernel_launch(void* const* d_in, const int* in_sizes, int n_in,
                              void* d_out, int out_size) {
    const float* x   = (const float*)d_in[0];
    const float* wq  = (const float*)d_in[1];
    const float* qg  = (const float*)d_in[2];
    const float* qb  = (const float*)d_in[3];
    const float* qm  = (const float*)d_in[4];
    const float* qv  = (const float*)d_in[5];
    const float* sg  = (const float*)d_in[6];
    const float* sb  = (const float*)d_in[7];
    const float* smn = (const float*)d_in[8];
    const float* svr = (const float*)d_in[9];
    const float* og  = (const float*)d_in[10];
    const float* ob  = (const float*)d_in[11];
    const float* om  = (const float*)d_in[12];
    const float* ov  = (const float*)d_in[13];
    float* out = (float*)d_out;

    cudaFuncSetAttribute(attn_fused_kernel,
                         cudaFuncAttributeMaxDynamicSharedMemorySize, SMEM_BYTES);

    attn_fused_kernel<<<2048, 256, SMEM_BYTES>>>(x, wq, qg, qb, qm, qv, sg, sb,
                                                 smn, svr, og, ob, om, ov);
    attn_transpose_kernel<<<3072, 256>>>(out);
}

// round 16
// speedup vs baseline: 1.0424x; 1.0063x over previous
#include <cuda_runtime.h>
#include <cuda_bf16.h>
#include <cuda_fp16.h>
#include <cstdint>

// NT=32, HS=64, WS=64 (K), CL=96 (l/j), OD=128 (o), G=8
// b = nt*64 + hs in [0,2048). One problem per CTA.
// Scratch layout: scr[b][cl][d]  (fp16; d contiguous)

__device__ __align__(16) __half g_scratch[2048 * 96 * 64];

__device__ __forceinline__ float ex2f(float x) {
    float r;
    asm("ex2.approx.f32 %0, %1;" : "=f"(r) : "f"(x));
    return r;
}
__device__ __forceinline__ float rcpf(float x) {
    float r;
    asm("rcp.approx.f32 %0, %1;" : "=f"(r) : "f"(x));
    return r;
}

__device__ __forceinline__ void mma_k16(float* d, const uint32_t* a,
                                        uint32_t b0, uint32_t b1) {
    asm volatile(
        "mma.sync.aligned.m16n8k16.row.col.f32.bf16.bf16.f32 "
        "{%0,%1,%2,%3}, {%4,%5,%6,%7}, {%8,%9}, {%0,%1,%2,%3};"
        : "+f"(d[0]), "+f"(d[1]), "+f"(d[2]), "+f"(d[3])
        : "r"(a[0]), "r"(a[1]), "r"(a[2]), "r"(a[3]), "r"(b0), "r"(b1));
}

__device__ __forceinline__ uint32_t bpack(float lo, float hi) {
    __nv_bfloat162 t = __float22bfloat162_rn(make_float2(lo, hi));
    return *(uint32_t*)&t;
}
__device__ __forceinline__ float blo(uint32_t hw) {
    return __uint_as_float(hw << 16);
}
__device__ __forceinline__ float bhi(uint32_t hw) {
    return __uint_as_float(hw & 0xFFFF0000u);
}

// split float4 into bf16-high / bf16-low, store 8B to each buffer
__device__ __forceinline__ void split8(char* hb, char* lb, uint32_t off, float4 v) {
    __nv_bfloat162 h0 = __float22bfloat162_rn(make_float2(v.x, v.y));
    __nv_bfloat162 h1 = __float22bfloat162_rn(make_float2(v.z, v.w));
    float2 f0 = __bfloat1622float2(h0), f1 = __bfloat1622float2(h1);
    __nv_bfloat162 l0 = __float22bfloat162_rn(make_float2(v.x - f0.x, v.y - f0.y));
    __nv_bfloat162 l1 = __float22bfloat162_rn(make_float2(v.z - f1.x, v.w - f1.y));
    uint2 hv, lv;
    hv.x = *(uint32_t*)&h0; hv.y = *(uint32_t*)&h1;
    lv.x = *(uint32_t*)&l0; lv.y = *(uint32_t*)&l1;
    *(uint2*)(hb + off) = hv;
    *(uint2*)(lb + off) = lv;
}

// ---------------- shared memory layout (bytes) ----------------
// X region (persistent, never aliased): rows stride 144B.
#define OFF_XH 0        // Xh: 96 x 144B = 13824
#define OFF_XL 13824    // Xl            -> end 27648
// Phase-2 region [27648, 108032): holds W (Ah/Al) during the prologue only;
// after all warps preload their A-fragments to registers (barrier 2), the
// region is re-used as per-warp attention buffers. No post-GEMM CTA barrier.
#define PH2    27648
#define OFF_AH 27648    // Wh: 128 x 144B = 18432
#define OFF_AL 46080    // Wl             -> end 64512 (inside phase-2 region)
// per-warp buffers, base PH2 + w*PWB:
//   Q: 96 rows x 36B; 16 bf16 slots = [qh(c0..3) | ql(c0..3) | qh(c0..3) | 0]
//   K: 96 rows x 36B; slots = [kh | kh | kl | 0]
//   VH/VL: 8 c-rows x 196B of bf16 over j (96 used)
#define PWB  10048
#define O_Q  0
#define O_K  3456
#define O_VH 6912
#define O_VL 8480       // end 10048; x8 warps = 80384 -> region end 108032
// coefficients, float indices from smem base (byte 108032+):
#define CAQ 27008
#define CBQ 27136
#define CAS 27264
#define CAO 27272
#define CBO 27336
#define SMEM_BYTES 109600

extern "C" __global__ void __launch_bounds__(256, 2)
attn_fused_kernel(const float* __restrict__ x, const float* __restrict__ w_qkv,
                  const float* __restrict__ qg, const float* __restrict__ qb,
                  const float* __restrict__ qm, const float* __restrict__ qv,
                  const float* __restrict__ sg, const float* __restrict__ sb,
                  const float* __restrict__ smn, const float* __restrict__ svr,
                  const float* __restrict__ og, const float* __restrict__ ob,
                  const float* __restrict__ om, const float* __restrict__ ov) {
    extern __shared__ __align__(16) char smemc[];
    float* smem = (float*)smemc;
    const int tid  = threadIdx.x;
    const int lane = tid & 31;
    const int w    = tid >> 5;
    const int b    = blockIdx.x;
    const int nt   = b >> 6;
    const int hs   = b & 63;
    const int r0   = lane >> 2;   // 0..7
    const int m4   = lane & 3;    // 0..3

    // ---- BN coefficient precompute ----
    if (tid < 128) {
        float a = qg[tid] * rsqrtf(qv[tid] + 1e-5f);
        smem[CAQ + tid] = a;
        smem[CBQ + tid] = qb[tid] - qm[tid] * a;
    }
    if (tid < 64) {
        float a = og[tid] * rsqrtf(ov[tid] + 1e-5f);
        smem[CAO + tid] = a;
        smem[CBO + tid] = ob[tid] - om[tid] * a;
    }
    if (tid < 8) {
        smem[CAS + tid] = sg[tid] * rsqrtf(svr[tid] + 1e-5f);
        (void)sb; (void)smn;  // sim BN bias cancels inside softmax
    }

    // ---- operand prep: W split (A, 128 rows(o) x 64 bf16(i)) ----
#pragma unroll
    for (int u = 0; u < 8; u++) {
        int idx4 = tid + 256 * u;
        int o = idx4 >> 4, i4 = idx4 & 15;
        float4 v = *(const float4*)(w_qkv + idx4 * 4);
        split8(smemc + OFF_AH, smemc + OFF_AL, o * 144 + i4 * 8, v);
    }
    // ---- operand prep: X split (B, 96 rows(l) x 64 bf16(i)) ----
    {
        const float* xbase = x + (size_t)nt * 393216 + (size_t)hs * 64;
#pragma unroll
        for (int u = 0; u < 6; u++) {
            int idx = tid + 256 * u;
            int i4 = idx & 15, l = idx >> 4;
            float4 v = *(const float4*)(xbase + (size_t)l * 4096 + i4 * 4);
            split8(smemc + OFF_XH, smemc + OFF_XL, l * 144 + i4 * 8, v);
        }
    }
    __syncthreads();   // barrier 1: W/X/coeffs visible

    // ---- preload A fragments (this warp's 16 W rows) into registers ----
    uint32_t ah[4][4], al[4][4];
    {
        const int qk2 = m4 * 4;
#pragma unroll
        for (int k = 0; k < 4; k++) {
            uint32_t off = (uint32_t)(16 * w + r0) * 144 + 32 * k + qk2;
            ah[k][0] = *(const uint32_t*)(smemc + OFF_AH + off);
            ah[k][1] = *(const uint32_t*)(smemc + OFF_AH + off + 8 * 144);
            ah[k][2] = *(const uint32_t*)(smemc + OFF_AH + off + 16);
            ah[k][3] = *(const uint32_t*)(smemc + OFF_AH + off + 8 * 144 + 16);
            al[k][0] = *(const uint32_t*)(smemc + OFF_AL + off);
            al[k][1] = *(const uint32_t*)(smemc + OFF_AL + off + 8 * 144);
            al[k][2] = *(const uint32_t*)(smemc + OFF_AL + off + 16);
            al[k][3] = *(const uint32_t*)(smemc + OFF_AL + off + 8 * 144 + 16);
        }
    }
    __syncthreads();   // barrier 2: W reads done; phase-2 region writable.
                       // From here on, warps are fully independent.

    char* wb = smemc + PH2 + w * PWB;

    // ---- zero the k-slot padding (bytes 24..31 of each Q/K row) ----
    // NOTE: 4-byte stores only — row*36+24 is 4-aligned but not 8-aligned.
#pragma unroll
    for (int u = 0; u < 3; u++) {
        int row = lane + 32 * u;
        *(uint32_t*)(wb + O_Q + row * 36 + 24) = 0u;
        *(uint32_t*)(wb + O_Q + row * 36 + 28) = 0u;
        *(uint32_t*)(wb + O_K + row * 36 + 24) = 0u;
        *(uint32_t*)(wb + O_K + row * 36 + 28) = 0u;
    }

    // ---- tensor-core QKV GEMM: warp w owns rows o in [16w, 16w+16) ----
    float d[12][4];
#pragma unroll
    for (int p = 0; p < 12; p++)
#pragma unroll
        for (int q = 0; q < 4; q++) d[p][q] = 0.f;
    {
        const int qk2 = m4 * 4;
#pragma unroll
        for (int k = 0; k < 4; k++)
#pragma unroll
            for (int p = 0; p < 6; p++) {
                uint32_t boff = (uint32_t)(16 * p + r0) * 144 + 32 * k + qk2;
                uint32_t b0 = *(const uint32_t*)(smemc + OFF_XH + boff);
                uint32_t b1 = *(const uint32_t*)(smemc + OFF_XH + boff + 16);
                uint32_t b2 = *(const uint32_t*)(smemc + OFF_XH + boff + 8 * 144);
                uint32_t b3 = *(const uint32_t*)(smemc + OFF_XH + boff + 8 * 144 + 16);
                mma_k16(d[2 * p],     ah[k], b0, b1);
                mma_k16(d[2 * p + 1], ah[k], b2, b3);
            }
#pragma unroll
        for (int k = 0; k < 4; k++)
#pragma unroll
            for (int p = 0; p < 6; p++) {
                uint32_t boff = (uint32_t)(16 * p + r0) * 144 + 32 * k + qk2;
                uint32_t b0 = *(const uint32_t*)(smemc + OFF_XL + boff);
                uint32_t b1 = *(const uint32_t*)(smemc + OFF_XL + boff + 16);
                uint32_t b2 = *(const uint32_t*)(smemc + OFF_XL + boff + 8 * 144);
                uint32_t b3 = *(const uint32_t*)(smemc + OFF_XL + boff + 8 * 144 + 16);
                mma_k16(d[2 * p],     ah[k], b0, b1);
                mma_k16(d[2 * p + 1], ah[k], b2, b3);
            }
#pragma unroll
        for (int k = 0; k < 4; k++)
#pragma unroll
            for (int p = 0; p < 6; p++) {
                uint32_t boff = (uint32_t)(16 * p + r0) * 144 + 32 * k + qk2;
                uint32_t b0 = *(const uint32_t*)(smemc + OFF_XH + boff);
                uint32_t b1 = *(const uint32_t*)(smemc + OFF_XH + boff + 16);
                uint32_t b2 = *(const uint32_t*)(smemc + OFF_XH + boff + 8 * 144);
                uint32_t b3 = *(const uint32_t*)(smemc + OFF_XH + boff + 8 * 144 + 16);
                mma_k16(d[2 * p],     al[k], b0, b1);
                mma_k16(d[2 * p + 1], al[k], b2, b3);
            }
    }

    // ---- epilogue: BN; q/k/v into this warp's attention buffers ----
    {
        const float sc = smem[CAS + w] * 1.4426950408889634f;  // ag/ln2
        const int o = 16 * w + r0;
        float A, B;
        if (r0 < 4) { A = smem[CAQ + o] * sc; B = smem[CBQ + o] * sc; }
        else        { A = smem[CAQ + o];      B = smem[CBQ + o]; }
        const float av = smem[CAQ + o + 8], bv = smem[CBQ + o + 8];
#pragma unroll
        for (int p = 0; p < 12; p++) {
            int l0 = 8 * p + 2 * m4;
            float v0 = d[p][0] * A + B, v1 = d[p][1] * A + B;
            __nv_bfloat16 h0 = __float2bfloat16_rn(v0);
            __nv_bfloat16 h1 = __float2bfloat16_rn(v1);
            __nv_bfloat16 g0 = __float2bfloat16_rn(v0 - __bfloat162float(h0));
            __nv_bfloat16 g1 = __float2bfloat16_rn(v1 - __bfloat162float(h1));
            if (r0 < 4) {
                int c = r0;
                char* q0p = wb + O_Q + l0 * 36;
                char* q1p = q0p + 36;
                *(__nv_bfloat16*)(q0p + 2 * c)       = h0;
                *(__nv_bfloat16*)(q0p + 2 * (8 + c)) = h0;
                *(__nv_bfloat16*)(q0p + 2 * (4 + c)) = g0;
                *(__nv_bfloat16*)(q1p + 2 * c)       = h1;
                *(__nv_bfloat16*)(q1p + 2 * (8 + c)) = h1;
                *(__nv_bfloat16*)(q1p + 2 * (4 + c)) = g1;
            } else {
                int c = r0 - 4;
                char* k0p = wb + O_K + l0 * 36;
                char* k1p = k0p + 36;
                *(__nv_bfloat16*)(k0p + 2 * c)       = h0;
                *(__nv_bfloat16*)(k0p + 2 * (4 + c)) = h0;
                *(__nv_bfloat16*)(k0p + 2 * (8 + c)) = g0;
                *(__nv_bfloat16*)(k1p + 2 * c)       = h1;
                *(__nv_bfloat16*)(k1p + 2 * (4 + c)) = h1;
                *(__nv_bfloat16*)(k1p + 2 * (8 + c)) = g1;
            }
            float vb0 = d[p][2] * av + bv, vb1 = d[p][3] * av + bv;
            uint32_t hv = bpack(vb0, vb1);
            uint32_t lv = bpack(vb0 - blo(hv), vb1 - bhi(hv));
            *(uint32_t*)(wb + O_VH + r0 * 196 + l0 * 2) = hv;
            *(uint32_t*)(wb + O_VL + r0 * 196 + l0 * 2) = lv;
        }
    }
    __syncwarp();   // buffers are warp-private

    // ---- HMMA attention: all-k16, two m-tiles interleaved per iteration ----
    {
        __half2* scr2 = (__half2*)(g_scratch + (size_t)b * 6144);
        const int d0 = 8 * w + 2 * m4;
        const int dh = d0 >> 1;
        const float ao0 = smem[CAO + d0],     bo0 = smem[CBO + d0];
        const float ao1 = smem[CAO + d0 + 1], bo1 = smem[CBO + d0 + 1];

#pragma unroll 1
        for (int tp = 0; tp < 3; tp++) {
            uint32_t qa0[4], qa1[4];
            {
                uint32_t qoff = (uint32_t)(32 * tp + r0) * 36 + 4 * m4;
                qa0[0] = *(const uint32_t*)(wb + O_Q + qoff);
                qa0[1] = *(const uint32_t*)(wb + O_Q + qoff + 8 * 36);
                qa0[2] = *(const uint32_t*)(wb + O_Q + qoff + 16);
                qa0[3] = *(const uint32_t*)(wb + O_Q + qoff + 8 * 36 + 16);
                uint32_t qoff1 = qoff + 16 * 36;
                qa1[0] = *(const uint32_t*)(wb + O_Q + qoff1);
                qa1[1] = *(const uint32_t*)(wb + O_Q + qoff1 + 8 * 36);
                qa1[2] = *(const uint32_t*)(wb + O_Q + qoff1 + 16);
                qa1[3] = *(const uint32_t*)(wb + O_Q + qoff1 + 8 * 36 + 16);
            }
            float a0A[4] = {0.f, 0.f, 0.f, 0.f}, a0B[4] = {0.f, 0.f, 0.f, 0.f};
            float a1A[4] = {0.f, 0.f, 0.f, 0.f}, a1B[4] = {0.f, 0.f, 0.f, 0.f};
            float s0_lo = 0.f, s0_hi = 0.f, s1_lo = 0.f, s1_hi = 0.f;

#pragma unroll 2
            for (int blk = 0; blk < 6; blk++) {
                uint32_t eh0[4], el0[4], eh1[4], el1[4];
#pragma unroll
                for (int sub = 0; sub < 2; sub++) {
                    int ch = 2 * blk + sub;
                    uint32_t koff = (uint32_t)(8 * ch + r0) * 36 + 4 * m4;
                    uint32_t kb0 = *(const uint32_t*)(wb + O_K + koff);
                    uint32_t kb1 = *(const uint32_t*)(wb + O_K + koff + 16);

                    float S0[4] = {0.f, 0.f, 0.f, 0.f};
                    float S1[4] = {0.f, 0.f, 0.f, 0.f};
                    mma_k16(S0, qa0, kb0, kb1);   // qh*kh + ql*kh + qh*kl
                    mma_k16(S1, qa1, kb0, kb1);

                    float e00 = ex2f(S0[0]), e01 = ex2f(S0[1]);
                    float e02 = ex2f(S0[2]), e03 = ex2f(S0[3]);
                    s0_lo += e00 + e01;
                    s0_hi += e02 + e03;
                    uint32_t p00 = bpack(e00, e01), p01 = bpack(e02, e03);
                    eh0[2 * sub]     = p00;
                    eh0[2 * sub + 1] = p01;
                    el0[2 * sub]     = bpack(e00 - blo(p00), e01 - bhi(p00));
                    el0[2 * sub + 1] = bpack(e02 - blo(p01), e03 - bhi(p01));

                    float e10 = ex2f(S1[0]), e11 = ex2f(S1[1]);
                    float e12 = ex2f(S1[2]), e13 = ex2f(S1[3]);
                    s1_lo += e10 + e11;
                    s1_hi += e12 + e13;
                    uint32_t p10 = bpack(e10, e11), p11 = bpack(e12, e13);
                    eh1[2 * sub]     = p10;
                    eh1[2 * sub + 1] = p11;
                    el1[2 * sub]     = bpack(e10 - blo(p10), e11 - bhi(p10));
                    el1[2 * sub + 1] = bpack(e12 - blo(p11), e13 - bhi(p11));
                }
                uint32_t voff = (uint32_t)r0 * 196 + 32 * blk + 4 * m4;
                uint32_t vh0 = *(const uint32_t*)(wb + O_VH + voff);
                uint32_t vh1 = *(const uint32_t*)(wb + O_VH + voff + 16);
                uint32_t vl0 = *(const uint32_t*)(wb + O_VL + voff);
                uint32_t vl1 = *(const uint32_t*)(wb + O_VL + voff + 16);
                mma_k16(a0A, eh0, vh0, vh1);
                mma_k16(a1A, eh1, vh0, vh1);
                mma_k16(a0B, el0, vh0, vh1);
                mma_k16(a1B, el1, vh0, vh1);
                mma_k16(a0B, eh0, vl0, vl1);
                mma_k16(a1B, eh1, vl0, vl1);
            }

            s0_lo += __shfl_xor_sync(0xffffffffu, s0_lo, 1);
            s0_lo += __shfl_xor_sync(0xffffffffu, s0_lo, 2);
            s0_hi += __shfl_xor_sync(0xffffffffu, s0_hi, 1);
            s0_hi += __shfl_xor_sync(0xffffffffu, s0_hi, 2);
            s1_lo += __shfl_xor_sync(0xffffffffu, s1_lo, 1);
            s1_lo += __shfl_xor_sync(0xffffffffu, s1_lo, 2);
            s1_hi += __shfl_xor_sync(0xffffffffu, s1_hi, 1);
            s1_hi += __shfl_xor_sync(0xffffffffu, s1_hi, 2);
            float r0l = rcpf(s0_lo), r0h = rcpf(s0_hi);
            float r1l = rcpf(s1_lo), r1h = rcpf(s1_hi);

            int i0 = 32 * tp + r0;
            scr2[i0 * 32 + dh] = __floats2half2_rn(
                (a0A[0] + a0B[0]) * r0l * ao0 + bo0,
                (a0A[1] + a0B[1]) * r0l * ao1 + bo1);
            scr2[(i0 + 8) * 32 + dh] = __floats2half2_rn(
                (a0A[2] + a0B[2]) * r0h * ao0 + bo0,
                (a0A[3] + a0B[3]) * r0h * ao1 + bo1);
            int i1 = i0 + 16;
            scr2[i1 * 32 + dh] = __floats2half2_rn(
                (a1A[0] + a1B[0]) * r1l * ao0 + bo0,
                (a1A[1] + a1B[1]) * r1l * ao1 + bo1);
            scr2[(i1 + 8) * 32 + dh] = __floats2half2_rn(
                (a1A[2] + a1B[2]) * r1h * ao0 + bo0,
                (a1A[3] + a1B[3]) * r1h * ao1 + bo1);
        }
    }
}

// Permute scr[(nt*64+hs)][cl][d] (fp16) -> out[((nt*96+cl)*64 + d)*64 + hs]
// One CTA per (nt, cl): reads 64(hs) x 64(d) fp16 tile, writes 4096 floats.
extern "C" __global__ void __launch_bounds__(256)
attn_transpose_kernel(float* __restrict__ out) {
    __shared__ uint32_t tile[64 * 33];   // fp16 rows: hs x 64d, stride 33 words
    const int nt = blockIdx.x / 96;
    const int cl = blockIdx.x % 96;

    const __half* src = g_scratch + ((size_t)nt * 64) * 6144 + cl * 64;
#pragma unroll
    for (int u = 0; u < 2; u++) {
        int idx = threadIdx.x + 256 * u;     // 0..511
        int hs = idx >> 3, d8 = idx & 7;
        uint4 v = *(const uint4*)(src + (size_t)hs * 6144 + 8 * d8);
        uint32_t* dst = &tile[33 * hs + 4 * d8];
        dst[0] = v.x; dst[1] = v.y; dst[2] = v.z; dst[3] = v.w;
    }
    __syncthreads();

    const __half* th = (const __half*)tile;   // index: hs*66 + d
    float* dst = out + ((size_t)nt * 96 + cl) * 4096;
#pragma unroll
    for (int u = 0; u < 4; u++) {
        int j = threadIdx.x + 256 * u;       // 0..1023
        int d = j >> 4, h4 = j & 15;
        float4 v;
        v.x = __half2float(th[(4 * h4 + 0) * 66 + d]);
        v.y = __half2float(th[(4 * h4 + 1) * 66 + d]);
        v.z = __half2float(th[(4 * h4 + 2) * 66 + d]);
        v.w = __half2float(th[(4 * h4 + 3) * 66 + d]);
        *(float4*)(dst + d * 64 + 4 * h4) = v;
    }
}

extern "C" void kernel_launch(void* const* d_in, const int* in_sizes, int n_in,
                              void* d_out, int out_size) {
    const float* x   = (const float*)d_in[0];
    const float* wq  = (const float*)d_in[1];
    const float* qg  = (const float*)d_in[2];
    const float* qb  = (const float*)d_in[3];
    const float* qm  = (const float*)d_in[4];
    const float* qv  = (const float*)d_in[5];
    const float* sg  = (const float*)d_in[6];
    const float* sb  = (const float*)d_in[7];
    const float* smn = (const float*)d_in[8];
    const float* svr = (const float*)d_in[9];
    const float* og  = (const float*)d_in[10];
    const float* ob  = (const float*)d_in[11];
    const float* om  = (const float*)d_in[12];
    const float* ov  = (const float*)d_in[13];
    float* out = (float*)d_out;

    cudaFuncSetAttribute(attn_fused_kernel,
                         cudaFuncAttributeMaxDynamicSharedMemorySize, SMEM_BYTES);

    attn_fused_kernel<<<2048, 256, SMEM_BYTES>>>(x, wq, qg, qb, qm, qv, sg, sb,
                                                 smn, svr, og, ob, om, ov);
    attn_transpose_kernel<<<3072, 256>>>(out);
}